// round 1
// baseline (speedup 1.0000x reference)
#include <cuda_runtime.h>
#include <math.h>

// Problem constants (fixed shapes)
#define DN 32
#define HN 192
#define WN 192
#define DHW (DN*HN*WN)      // 1179648
#define BN 4
#define CN 7
#define NID 16
#define NBI (BN*NID)        // 64
#define NB 4096             // histogram bins over e in [0,2]
#define SLICES 8
#define CHUNK (DHW/SLICES)  // 147456

// ---------------- device scratch (static; no allocations) ----------------
__device__ float4 g_se[(size_t)BN*DHW];          // tanh(pred[:3])+xyzm, seed  (75.5MB)
__device__ int    g_hcnt[NBI][2*NB];             // [gt*NB+bin] counts
__device__ float  g_hsum[NBI][2*NB];             // [gt*NB+bin] sum of errors
__device__ double g_acc[NBI][10];                // cnt, sum_xyz[3], sum_sig[3], sum_sig2[3]
__device__ double g_bg[BN];
__device__ double g_seedl[BN];
__device__ double g_instl[BN];
__device__ float  g_center[NBI][3];
__device__ float  g_sexp[NBI][3];
__device__ float  g_cnt[NBI];
__device__ float  g_varsum[BN];
__device__ float  g_denom[BN];

// ---------------- zero scratch ----------------
__global__ void kzero() {
    size_t tid0 = (size_t)blockIdx.x * blockDim.x + threadIdx.x;
    size_t stride = (size_t)gridDim.x * blockDim.x;
    int*   hc = &g_hcnt[0][0];
    float* hs = &g_hsum[0][0];
    size_t n = (size_t)NBI * 2 * NB;
    for (size_t i = tid0; i < n; i += stride) { hc[i] = 0; hs[i] = 0.f; }
    double* acc = &g_acc[0][0];
    for (size_t i = tid0; i < (size_t)NBI * 10; i += stride) acc[i] = 0.0;
    if (tid0 < BN) { g_bg[tid0] = 0.0; g_seedl[tid0] = 0.0; g_instl[tid0] = 0.0; }
}

// ---------------- pass 1: preprocess + per-instance accumulators ----------------
__global__ void k1(const float* __restrict__ pred, const int* __restrict__ inst,
                   const int* __restrict__ lab, const float* __restrict__ xyzm) {
    __shared__ float sacc[NID*10];
    __shared__ float sbg;
    int tid = threadIdx.x;
    for (int i = tid; i < NID*10; i += blockDim.x) sacc[i] = 0.f;
    if (tid == 0) sbg = 0.f;
    __syncthreads();

    int b = blockIdx.y;
    const float* pb = pred + (size_t)b * CN * DHW;
    const int*   ib = inst + (size_t)b * DHW;
    const int*   lb = lab  + (size_t)b * DHW;
    float bgl = 0.f;

    for (int v = blockIdx.x * blockDim.x + tid; v < DHW; v += gridDim.x * blockDim.x) {
        float p0 = pb[v], p1 = pb[DHW+v], p2 = pb[2*DHW+v];
        float s0 = pb[3*DHW+v], s1 = pb[4*DHW+v], s2 = pb[5*DHW+v];
        float p6 = pb[6*DHW+v];
        float xm = xyzm[v], ym = xyzm[DHW+v], zm = xyzm[2*DHW+v];
        float e0 = tanhf(p0) + xm;
        float e1 = tanhf(p1) + ym;
        float e2 = tanhf(p2) + zm;
        float seed = 1.f / (1.f + __expf(-p6));
        g_se[(size_t)b*DHW + v] = make_float4(e0, e1, e2, seed);

        int id = ib[v];
        if (id > 0) {
            float* s = &sacc[(id-1)*10];
            atomicAdd(s+0, 1.f);
            atomicAdd(s+1, xm); atomicAdd(s+2, ym); atomicAdd(s+3, zm);
            atomicAdd(s+4, s0); atomicAdd(s+5, s1); atomicAdd(s+6, s2);
            atomicAdd(s+7, s0*s0); atomicAdd(s+8, s1*s1); atomicAdd(s+9, s2*s2);
        }
        if (lb[v] == 0) bgl += seed * seed;
    }
    atomicAdd(&sbg, bgl);
    __syncthreads();

    for (int i = tid; i < NID*10; i += blockDim.x)
        atomicAdd(&g_acc[b*NID + i/10][i%10], (double)sacc[i]);
    if (tid == 0) atomicAdd(&g_bg[b], (double)sbg);
}

// ---------------- pass 2: per-instance stats ----------------
__global__ void k2() {
    __shared__ float sobj[BN], svar[BN];
    int t = threadIdx.x;            // 0..63  (b*16 + (id-1))
    if (t < BN) { sobj[t] = 0.f; svar[t] = 0.f; }
    __syncthreads();
    int b = t / NID;

    double cnt = g_acc[t][0];
    bool ex = cnt > 0.0;
    double safe = cnt > 1.0 ? cnt : 1.0;
    double c0 = g_acc[t][1] / safe, c1 = g_acc[t][2] / safe, c2 = g_acc[t][3] / safe;
    double m0 = g_acc[t][4] / safe, m1 = g_acc[t][5] / safe, m2 = g_acc[t][6] / safe;
    double var = 0.0;
    if (ex) {
        var = ((g_acc[t][7] - cnt*m0*m0) +
               (g_acc[t][8] - cnt*m1*m1) +
               (g_acc[t][9] - cnt*m2*m2)) / (3.0 * safe);
    }
    g_center[t][0] = (float)c0; g_center[t][1] = (float)c1; g_center[t][2] = (float)c2;
    g_sexp[t][0] = expf((float)(m0 * 10.0));
    g_sexp[t][1] = expf((float)(m1 * 10.0));
    g_sexp[t][2] = expf((float)(m2 * 10.0));
    g_cnt[t] = ex ? (float)cnt : 0.f;

    atomicAdd(&sobj[b], ex ? 1.f : 0.f);
    atomicAdd(&svar[b], (float)var);
    __syncthreads();
    if (t < BN) {
        g_denom[t]  = sobj[t] > 1.f ? sobj[t] : 1.f;
        g_varsum[t] = svar[t];
    }
}

// ---------------- pass 3: per-(b,id) histograms + seed loss ----------------
__global__ void k3(const int* __restrict__ inst) {
    extern __shared__ int smem[];
    int*   scnt = smem;                       // 2*NB ints
    float* ssum = (float*)(smem + 2*NB);      // 2*NB floats
    __shared__ float sred;

    int b = blockIdx.z, idm1 = blockIdx.x;
    int bi = b * NID + idm1;
    int id = idm1 + 1;
    float G = g_cnt[bi];
    if (G == 0.f) return;

    float c0 = g_center[bi][0], c1 = g_center[bi][1], c2 = g_center[bi][2];
    float e0 = g_sexp[bi][0],   e1 = g_sexp[bi][1],   e2 = g_sexp[bi][2];

    int tid = threadIdx.x;
    for (int i = tid; i < 2*NB; i += blockDim.x) { scnt[i] = 0; ssum[i] = 0.f; }
    if (tid == 0) sred = 0.f;
    __syncthreads();

    const float4* se = g_se + (size_t)b * DHW;
    const int*    ib = inst + (size_t)b * DHW;
    float sacc = 0.f;
    int v0 = blockIdx.y * CHUNK;
    for (int v = v0 + tid; v < v0 + CHUNK; v += blockDim.x) {
        float4 s = se[v];
        int gt = (ib[v] == id);
        float dx = s.x - c0, dy = s.y - c1, dz = s.z - c2;
        float d2 = dx*dx*e0 + dy*dy*e1 + dz*dz*e2;
        float dist = __expf(-d2);
        float e = gt ? (2.f - 2.f*dist) : (2.f*dist);
        int bin = (int)(e * (NB * 0.5f));
        bin = bin > NB-1 ? NB-1 : (bin < 0 ? 0 : bin);
        int off = gt * NB + bin;
        atomicAdd(&scnt[off], 1);
        atomicAdd(&ssum[off], e);
        if (gt) { float df = s.w - dist; sacc += df * df; }
    }
    atomicAdd(&sred, sacc);
    __syncthreads();
    if (tid == 0) atomicAdd(&g_seedl[b], (double)sred);
    for (int i = tid; i < 2*NB; i += blockDim.x) {
        int c = scnt[i];
        if (c) {
            atomicAdd(&g_hcnt[bi][i], c);
            atomicAdd(&g_hsum[bi][i], ssum[i]);
        }
    }
}

// ---------------- pass 4: Lovasz via histogram scan ----------------
#define NT4 512
#define PER4 (NB / NT4)   // 8
__global__ void k4() {
    int bi = blockIdx.x, b = bi / NID;
    float G = g_cnt[bi];
    if (G == 0.f) return;
    int t = threadIdx.x;
    __shared__ float sp[NT4], sn[NT4];
    __shared__ double sctr[NT4];

    int base = t * PER4;
    float tp = 0.f, tn = 0.f;
    #pragma unroll
    for (int i = 0; i < PER4; i++) {
        int j = NB - 1 - (base + i);                 // descending error order
        tp += (float)g_hcnt[bi][NB + j];             // positives (gt=1)
        tn += (float)g_hcnt[bi][j];                  // negatives (gt=0)
    }
    sp[t] = tp; sn[t] = tn;
    __syncthreads();
    for (int o = 1; o < NT4; o <<= 1) {
        float ap = (t >= o) ? sp[t - o] : 0.f;
        float an = (t >= o) ? sn[t - o] : 0.f;
        __syncthreads();
        sp[t] += ap; sn[t] += an;
        __syncthreads();
    }
    float P = sp[t] - tp;   // exclusive cumulative positives before this thread's bins
    float N = sn[t] - tn;

    double contrib = 0.0;
    #pragma unroll
    for (int i = 0; i < PER4; i++) {
        int j = NB - 1 - (base + i);
        float p = (float)g_hcnt[bi][NB + j];
        float n = (float)g_hcnt[bi][j];
        float U0 = G + N;
        // positives first within bin: sum_e_pos * (J(P+p,N) - J(P,N)) / ... = esum_p / (G+N)
        if (p > 0.f) contrib += (double)g_hsum[bi][NB + j] / (double)U0;
        float P1 = P + p;
        // then negatives: esum_n * (G-P1) / ((G+N)(G+N+n))
        if (n > 0.f) contrib += (double)g_hsum[bi][j] * (double)(G - P1)
                                / ((double)U0 * (double)(U0 + n));
        P = P1; N += n;
    }
    sctr[t] = contrib;
    __syncthreads();
    for (int o = NT4/2; o > 0; o >>= 1) {
        if (t < o) sctr[t] += sctr[t + o];
        __syncthreads();
    }
    if (t == 0) atomicAdd(&g_instl[b], sctr[0]);
}

// ---------------- pass 5: final reduction ----------------
__global__ void k5(float* __restrict__ out) {
    double li = 0.0, lv = 0.0, ls = 0.0;
    for (int b = 0; b < BN; b++) {
        li += g_instl[b] / (double)g_denom[b];
        lv += (double)g_varsum[b] / (double)g_denom[b];
        ls += (g_seedl[b] + g_bg[b]) / (double)DHW;
    }
    li /= (double)BN;
    lv = lv * 10.0 / (double)BN;   // W_VAR = 10
    ls /= (double)BN;
    out[0] = (float)li;
    out[1] = (float)lv;
    out[2] = (float)ls;
    out[3] = (float)(li + lv + ls);
}

// ---------------- launch ----------------
extern "C" void kernel_launch(void* const* d_in, const int* in_sizes, int n_in,
                              void* d_out, int out_size) {
    const float* pred = (const float*)d_in[0];
    const int*   inst = (const int*)d_in[1];
    const int*   lab  = (const int*)d_in[2];
    // d_in[3] = center_images (unused by the loss)
    const float* xyzm = (const float*)d_in[4];

    cudaFuncSetAttribute(k3, cudaFuncAttributeMaxDynamicSharedMemorySize, 2*NB*8);

    kzero<<<512, 256>>>();
    k1<<<dim3(288, BN), 256>>>(pred, inst, lab, xyzm);
    k2<<<1, 64>>>();
    k3<<<dim3(NID, SLICES, BN), 256, 2*NB*8>>>(inst);
    k4<<<NBI, NT4>>>();
    k5<<<1, 1>>>((float*)d_out);
}

// round 2
// speedup vs baseline: 1.1046x; 1.1046x over previous
#include <cuda_runtime.h>
#include <math.h>

// Problem constants (fixed shapes)
#define DN 32
#define HN 192
#define WN 192
#define DHW (DN*HN*WN)      // 1179648
#define BN 4
#define CN 7
#define NID 16
#define NBI (BN*NID)        // 64
#define NB 4096             // histogram bins over e in [0,2]
#define SLICES 5
#define CH ((DHW + SLICES - 1) / SLICES)   // 235930

// ---------------- device scratch (static; no allocations) ----------------
__device__ float4 g_se[(size_t)BN*DHW];          // tanh(pred[:3])+xyzm, seed  (75.5MB)
__device__ int    g_hcnt[NBI][2*NB];             // [gt*NB+bin] counts
__device__ float  g_hsum[NBI][2*NB];             // [gt*NB+bin] sum of errors
__device__ double g_acc[NBI][10];                // cnt, sum_xyz[3], sum_sig[3], sum_sig2[3]
__device__ double g_bg[BN];
__device__ double g_seedl[BN];
__device__ double g_instl[BN];
__device__ float  g_center[NBI][3];
__device__ float  g_sexp[NBI][3];
__device__ float  g_cnt[NBI];
__device__ float  g_varsum[BN];
__device__ float  g_denom[BN];

// ---------------- zero scratch ----------------
__global__ void kzero() {
    size_t tid0 = (size_t)blockIdx.x * blockDim.x + threadIdx.x;
    size_t stride = (size_t)gridDim.x * blockDim.x;
    int*   hc = &g_hcnt[0][0];
    float* hs = &g_hsum[0][0];
    size_t n = (size_t)NBI * 2 * NB;
    for (size_t i = tid0; i < n; i += stride) { hc[i] = 0; hs[i] = 0.f; }
    double* acc = &g_acc[0][0];
    for (size_t i = tid0; i < (size_t)NBI * 10; i += stride) acc[i] = 0.0;
    if (tid0 < BN) { g_bg[tid0] = 0.0; g_seedl[tid0] = 0.0; g_instl[tid0] = 0.0; }
}

// fixed-point packing helper: hi field << 32 | lo field (round-to-nearest)
__device__ __forceinline__ unsigned long long pk2(float hi, float lo) {
    return ((unsigned long long)__float2uint_rn(hi) << 32) | (unsigned long long)__float2uint_rn(lo);
}

// ---------------- pass 1: preprocess + per-instance accumulators ----------------
// packed shared accumulators per id (5 u64 atomics per fg voxel instead of 10 f32):
//   [0] x<<32 | y          (scale 2^20, values in [0,1])
//   [1] z<<32 | (s0+16)    (z scale 2^20, sigma scale 2^15 biased +16)
//   [2] (s1+16)<<32 | (s2+16)   (scale 2^15)
//   [3] s0^2<<32 | s1^2    (scale 2^14)
//   [4] s2^2<<32 | cnt     (scale 2^14, cnt plain)
#define SCP 1048576.0f   // 2^20
#define SCS 32768.0f     // 2^15
#define SCQ 16384.0f     // 2^14
__global__ void __launch_bounds__(1024) k1(const float* __restrict__ pred, const int* __restrict__ inst,
                   const int* __restrict__ lab, const float* __restrict__ xyzm) {
    __shared__ unsigned long long sacc[NID][5];
    __shared__ float swr[32];
    int tid = threadIdx.x;
    if (tid < NID*5) sacc[tid/5][tid%5] = 0ULL;
    __syncthreads();

    int b = blockIdx.y;
    const float* pb = pred + (size_t)b * CN * DHW;
    const int*   ib = inst + (size_t)b * DHW;
    const int*   lb = lab  + (size_t)b * DHW;
    float bgl = 0.f;

    for (int v = blockIdx.x * blockDim.x + tid; v < DHW; v += gridDim.x * blockDim.x) {
        float p0 = pb[v], p1 = pb[DHW+v], p2 = pb[2*DHW+v];
        float s0 = pb[3*DHW+v], s1 = pb[4*DHW+v], s2 = pb[5*DHW+v];
        float p6 = pb[6*DHW+v];
        float xm = xyzm[v], ym = xyzm[DHW+v], zm = xyzm[2*DHW+v];
        float e0 = tanhf(p0) + xm;
        float e1 = tanhf(p1) + ym;
        float e2 = tanhf(p2) + zm;
        float seed = 1.f / (1.f + __expf(-p6));
        g_se[(size_t)b*DHW + v] = make_float4(e0, e1, e2, seed);

        int id = ib[v];
        if (id > 0) {
            unsigned long long* s = sacc[id-1];
            atomicAdd(&s[0], pk2(xm*SCP, ym*SCP));
            atomicAdd(&s[1], pk2(zm*SCP, (s0+16.f)*SCS));
            atomicAdd(&s[2], pk2((s1+16.f)*SCS, (s2+16.f)*SCS));
            atomicAdd(&s[3], pk2(s0*s0*SCQ, s1*s1*SCQ));
            atomicAdd(&s[4], (((unsigned long long)__float2uint_rn(s2*s2*SCQ)) << 32) | 1ULL);
        }
        if (lb[v] == 0) bgl += seed * seed;
    }
    // warp-reduce bg
    for (int o = 16; o; o >>= 1) bgl += __shfl_down_sync(0xffffffffu, bgl, o);
    if ((tid & 31) == 0) swr[tid >> 5] = bgl;
    __syncthreads();
    if (tid == 0) {
        double s = 0.0;
        for (int i = 0; i < 32; i++) s += (double)swr[i];
        atomicAdd(&g_bg[b], s);
    }
    // decode + merge (16 ids, thread i handles id i)
    if (tid < NID) {
        unsigned long long A = sacc[tid][0], Bv = sacc[tid][1], Cv = sacc[tid][2],
                           Dv = sacc[tid][3], E = sacc[tid][4];
        const double M = 4294967295.0; (void)M;
        double cnt = (double)(unsigned)(E & 0xffffffffULL);
        double sx = (double)(unsigned)(A >> 32) / (double)SCP;
        double sy = (double)(unsigned)(A & 0xffffffffULL) / (double)SCP;
        double sz = (double)(unsigned)(Bv >> 32) / (double)SCP;
        double ss0 = (double)(unsigned)(Bv & 0xffffffffULL) / (double)SCS - 16.0 * cnt;
        double ss1 = (double)(unsigned)(Cv >> 32) / (double)SCS - 16.0 * cnt;
        double ss2 = (double)(unsigned)(Cv & 0xffffffffULL) / (double)SCS - 16.0 * cnt;
        double q0 = (double)(unsigned)(Dv >> 32) / (double)SCQ;
        double q1 = (double)(unsigned)(Dv & 0xffffffffULL) / (double)SCQ;
        double q2 = (double)(unsigned)(E >> 32) / (double)SCQ;
        double* g = g_acc[b*NID + tid];
        if (cnt > 0.0) {
            atomicAdd(&g[0], cnt);
            atomicAdd(&g[1], sx); atomicAdd(&g[2], sy); atomicAdd(&g[3], sz);
            atomicAdd(&g[4], ss0); atomicAdd(&g[5], ss1); atomicAdd(&g[6], ss2);
            atomicAdd(&g[7], q0); atomicAdd(&g[8], q1); atomicAdd(&g[9], q2);
        }
    }
}

// ---------------- pass 2: per-instance stats ----------------
__global__ void k2() {
    __shared__ float sobj[BN], svar[BN];
    int t = threadIdx.x;            // 0..63  (b*16 + (id-1))
    if (t < BN) { sobj[t] = 0.f; svar[t] = 0.f; }
    __syncthreads();
    int b = t / NID;

    double cnt = g_acc[t][0];
    bool ex = cnt > 0.0;
    double safe = cnt > 1.0 ? cnt : 1.0;
    double c0 = g_acc[t][1] / safe, c1 = g_acc[t][2] / safe, c2 = g_acc[t][3] / safe;
    double m0 = g_acc[t][4] / safe, m1 = g_acc[t][5] / safe, m2 = g_acc[t][6] / safe;
    double var = 0.0;
    if (ex) {
        var = ((g_acc[t][7] - cnt*m0*m0) +
               (g_acc[t][8] - cnt*m1*m1) +
               (g_acc[t][9] - cnt*m2*m2)) / (3.0 * safe);
    }
    g_center[t][0] = (float)c0; g_center[t][1] = (float)c1; g_center[t][2] = (float)c2;
    g_sexp[t][0] = expf((float)(m0 * 10.0));
    g_sexp[t][1] = expf((float)(m1 * 10.0));
    g_sexp[t][2] = expf((float)(m2 * 10.0));
    g_cnt[t] = ex ? (float)cnt : 0.f;

    atomicAdd(&sobj[b], ex ? 1.f : 0.f);
    atomicAdd(&svar[b], (float)var);
    __syncthreads();
    if (t < BN) {
        g_denom[t]  = sobj[t] > 1.f ? sobj[t] : 1.f;
        g_varsum[t] = svar[t];
    }
}

// ---------------- pass 3: per-(b,id) histograms + seed loss ----------------
// one packed u64 shared atomic per voxel: (count << 32) | residual
// t = e * 2048 in [0,4096); bin = floor(t); residual = frac(t) in 1/16384 units
__global__ void __launch_bounds__(1024, 2) k3(const int* __restrict__ inst) {
    extern __shared__ unsigned long long sh[];     // 2*NB u64 = 64KB
    __shared__ float swr[32];

    int b = blockIdx.z, idm1 = blockIdx.x;
    int bi = b * NID + idm1;
    int id = idm1 + 1;
    float G = g_cnt[bi];
    if (G == 0.f) return;

    float c0 = g_center[bi][0], c1 = g_center[bi][1], c2 = g_center[bi][2];
    float e0 = g_sexp[bi][0],   e1 = g_sexp[bi][1],   e2 = g_sexp[bi][2];

    int tid = threadIdx.x;
    for (int i = tid; i < 2*NB; i += blockDim.x) sh[i] = 0ULL;
    __syncthreads();

    const float4* se = g_se + (size_t)b * DHW;
    const int*    ib = inst + (size_t)b * DHW;
    float sacc = 0.f;
    int v0 = blockIdx.y * CH;
    int vend = v0 + CH; if (vend > DHW) vend = DHW;
    for (int v = v0 + tid; v < vend; v += blockDim.x) {
        float4 s = se[v];
        bool gt = (ib[v] == id);
        float dx = s.x - c0, dy = s.y - c1, dz = s.z - c2;
        float d2 = dx*dx*e0 + dy*dy*e1 + dz*dz*e2;
        float dist = __expf(-d2);
        float t = gt ? 4096.f * (1.f - dist) : 4096.f * dist;
        int bin = (int)t;
        bin = bin > NB-1 ? NB-1 : (bin < 0 ? 0 : bin);
        float frac = t - (float)bin;
        frac = frac < 0.f ? 0.f : (frac > 0.99993f ? 0.99993f : frac);
        unsigned fx = (unsigned)(frac * 16384.f);
        atomicAdd(&sh[(gt ? NB : 0) + bin], (1ULL << 32) | (unsigned long long)fx);
        if (gt) { float df = s.w - dist; sacc += df * df; }
    }
    // warp-reduce seed loss
    for (int o = 16; o; o >>= 1) sacc += __shfl_down_sync(0xffffffffu, sacc, o);
    if ((tid & 31) == 0) swr[tid >> 5] = sacc;
    __syncthreads();
    if (tid == 0) {
        double s = 0.0;
        for (int i = 0; i < 32; i++) s += (double)swr[i];
        atomicAdd(&g_seedl[b], s);
    }
    // decode + merge to global histograms
    for (int i = tid; i < 2*NB; i += blockDim.x) {
        unsigned long long v = sh[i];
        if (v) {
            unsigned c = (unsigned)(v >> 32);
            double lowsum = (double)(unsigned)(v & 0xffffffffULL);
            int bin = i & (NB - 1);
            double esum = ((double)c * (double)bin + lowsum * (1.0/16384.0)) * (1.0/2048.0);
            atomicAdd(&g_hcnt[bi][i], (int)c);
            atomicAdd(&g_hsum[bi][i], (float)esum);
        }
    }
}

// ---------------- pass 4: Lovasz via histogram scan ----------------
#define NT4 512
#define PER4 (NB / NT4)   // 8
__global__ void k4() {
    int bi = blockIdx.x, b = bi / NID;
    float G = g_cnt[bi];
    if (G == 0.f) return;
    int t = threadIdx.x;
    __shared__ float sp[NT4], sn[NT4];
    __shared__ double sctr[NT4];

    int base = t * PER4;
    float tp = 0.f, tn = 0.f;
    #pragma unroll
    for (int i = 0; i < PER4; i++) {
        int j = NB - 1 - (base + i);                 // descending error order
        tp += (float)g_hcnt[bi][NB + j];             // positives (gt=1)
        tn += (float)g_hcnt[bi][j];                  // negatives (gt=0)
    }
    sp[t] = tp; sn[t] = tn;
    __syncthreads();
    for (int o = 1; o < NT4; o <<= 1) {
        float ap = (t >= o) ? sp[t - o] : 0.f;
        float an = (t >= o) ? sn[t - o] : 0.f;
        __syncthreads();
        sp[t] += ap; sn[t] += an;
        __syncthreads();
    }
    float P = sp[t] - tp;   // exclusive cumulative positives before this thread's bins
    float N = sn[t] - tn;

    double contrib = 0.0;
    #pragma unroll
    for (int i = 0; i < PER4; i++) {
        int j = NB - 1 - (base + i);
        float p = (float)g_hcnt[bi][NB + j];
        float n = (float)g_hcnt[bi][j];
        double U0 = (double)G + (double)N;
        double U1 = U0 + (double)n;
        // average of pos-first and neg-first within-bin orderings:
        if (p > 0.f) contrib += (double)g_hsum[bi][NB + j] * 0.5 * (1.0/U0 + 1.0/U1);
        if (n > 0.f) contrib += (double)g_hsum[bi][j] *
                                ((double)G - (double)P - 0.5*(double)p) / (U0 * U1);
        P += p; N += n;
    }
    sctr[t] = contrib;
    __syncthreads();
    for (int o = NT4/2; o > 0; o >>= 1) {
        if (t < o) sctr[t] += sctr[t + o];
        __syncthreads();
    }
    if (t == 0) atomicAdd(&g_instl[b], sctr[0]);
}

// ---------------- pass 5: final reduction ----------------
__global__ void k5(float* __restrict__ out) {
    double li = 0.0, lv = 0.0, ls = 0.0;
    for (int b = 0; b < BN; b++) {
        li += g_instl[b] / (double)g_denom[b];
        lv += (double)g_varsum[b] / (double)g_denom[b];
        ls += (g_seedl[b] + g_bg[b]) / (double)DHW;
    }
    li /= (double)BN;
    lv = lv * 10.0 / (double)BN;   // W_VAR = 10
    ls /= (double)BN;
    out[0] = (float)li;
    out[1] = (float)lv;
    out[2] = (float)ls;
    out[3] = (float)(li + lv + ls);
}

// ---------------- launch ----------------
extern "C" void kernel_launch(void* const* d_in, const int* in_sizes, int n_in,
                              void* d_out, int out_size) {
    const float* pred = (const float*)d_in[0];
    const int*   inst = (const int*)d_in[1];
    const int*   lab  = (const int*)d_in[2];
    // d_in[3] = center_images (unused by the loss)
    const float* xyzm = (const float*)d_in[4];

    cudaFuncSetAttribute(k3, cudaFuncAttributeMaxDynamicSharedMemorySize, 2*NB*8);

    kzero<<<512, 256>>>();
    k1<<<dim3(64, BN), 1024>>>(pred, inst, lab, xyzm);
    k2<<<1, 64>>>();
    k3<<<dim3(NID, SLICES, BN), 1024, 2*NB*8>>>(inst);
    k4<<<NBI, NT4>>>();
    k5<<<1, 1>>>((float*)d_out);
}

// round 4
// speedup vs baseline: 1.8356x; 1.6617x over previous
#include <cuda_runtime.h>
#include <math.h>

// Problem constants (fixed shapes)
#define DN 32
#define HN 192
#define WN 192
#define DHW (DN*HN*WN)      // 1179648
#define BN 4
#define CN 7
#define NID 16
#define NBI (BN*NID)        // 64
#define NB 4096             // histogram bins over e in [0,2]
#define SLICES 7
#define CH ((DHW + SLICES - 1) / SLICES)   // 168522

// ---------------- device scratch (static; no allocations) ----------------
__device__ float4 g_se[(size_t)BN*DHW];                  // tanh(pred[:3])+xyzm, seed
__device__ unsigned char g_id8[(size_t)BN*DHW];          // compact instance ids
__device__ unsigned long long g_part[NBI][SLICES][2*NB]; // per-slice packed histograms
__device__ double g_acc[NBI][10];
__device__ double g_bg[BN];
__device__ double g_seedl[BN];
__device__ double g_instl[BN];
__device__ float  g_center[NBI][3];
__device__ float  g_sexp[NBI][3];
__device__ float  g_cnt[NBI];
__device__ float  g_varsum[BN];
__device__ float  g_denom[BN];

// ---------------- zero the small accumulators only ----------------
__global__ void kzero() {
    int t = threadIdx.x;
    double* acc = &g_acc[0][0];
    if (t < NBI*10) acc[t] = 0.0;
    if (t < BN) { g_bg[t] = 0.0; g_seedl[t] = 0.0; g_instl[t] = 0.0; }
}

// ---------------- pass 1: preprocess + per-instance accumulators ----------------
__global__ void __launch_bounds__(256) k1(const float* __restrict__ pred,
                                          const int* __restrict__ inst,
                                          const int* __restrict__ lab,
                                          const float* __restrict__ xyzm) {
    __shared__ float sacc[2][NID*10];    // 2 replicas to halve contention
    __shared__ float swr[8];
    int tid = threadIdx.x;
    for (int i = tid; i < 2*NID*10; i += blockDim.x) sacc[i/(NID*10)][i%(NID*10)] = 0.f;
    __syncthreads();
    int rep = (tid >> 5) & 1;

    int b = blockIdx.y;
    const float* pb = pred + (size_t)b * CN * DHW;
    const int*   ib = inst + (size_t)b * DHW;
    const int*   lb = lab  + (size_t)b * DHW;
    float bgl = 0.f;

    for (int v = blockIdx.x * blockDim.x + tid; v < DHW; v += gridDim.x * blockDim.x) {
        float p0 = pb[v], p1 = pb[DHW+v], p2 = pb[2*DHW+v];
        float s0 = pb[3*DHW+v], s1 = pb[4*DHW+v], s2 = pb[5*DHW+v];
        float p6 = pb[6*DHW+v];
        float xm = xyzm[v], ym = xyzm[DHW+v], zm = xyzm[2*DHW+v];
        float e0 = tanhf(p0) + xm;
        float e1 = tanhf(p1) + ym;
        float e2 = tanhf(p2) + zm;
        float seed = 1.f / (1.f + __expf(-p6));
        g_se[(size_t)b*DHW + v] = make_float4(e0, e1, e2, seed);

        int id = ib[v];
        g_id8[(size_t)b*DHW + v] = (unsigned char)id;
        if (id > 0) {
            float* s = &sacc[rep][(id-1)*10];
            atomicAdd(s+0, 1.f);
            atomicAdd(s+1, xm); atomicAdd(s+2, ym); atomicAdd(s+3, zm);
            atomicAdd(s+4, s0); atomicAdd(s+5, s1); atomicAdd(s+6, s2);
            atomicAdd(s+7, s0*s0); atomicAdd(s+8, s1*s1); atomicAdd(s+9, s2*s2);
        }
        if (lb[v] == 0) bgl += seed * seed;
    }
    // warp-reduce bg
    for (int o = 16; o; o >>= 1) bgl += __shfl_down_sync(0xffffffffu, bgl, o);
    if ((tid & 31) == 0) swr[tid >> 5] = bgl;
    __syncthreads();
    if (tid == 0) {
        double s = 0.0;
        for (int i = 0; i < 8; i++) s += (double)swr[i];
        atomicAdd(&g_bg[b], s);
    }
    for (int i = tid; i < NID*10; i += blockDim.x) {
        float v2 = sacc[0][i] + sacc[1][i];
        atomicAdd(&g_acc[b*NID + i/10][i%10], (double)v2);
    }
}

// ---------------- pass 2: per-instance stats ----------------
__global__ void k2() {
    __shared__ float sobj[BN], svar[BN];
    int t = threadIdx.x;            // 0..63  (b*16 + (id-1))
    if (t < BN) { sobj[t] = 0.f; svar[t] = 0.f; }
    __syncthreads();
    int b = t / NID;

    double cnt = g_acc[t][0];
    bool ex = cnt > 0.0;
    double safe = cnt > 1.0 ? cnt : 1.0;
    double c0 = g_acc[t][1] / safe, c1 = g_acc[t][2] / safe, c2 = g_acc[t][3] / safe;
    double m0 = g_acc[t][4] / safe, m1 = g_acc[t][5] / safe, m2 = g_acc[t][6] / safe;
    double var = 0.0;
    if (ex) {
        var = ((g_acc[t][7] - cnt*m0*m0) +
               (g_acc[t][8] - cnt*m1*m1) +
               (g_acc[t][9] - cnt*m2*m2)) / (3.0 * safe);
    }
    g_center[t][0] = (float)c0; g_center[t][1] = (float)c1; g_center[t][2] = (float)c2;
    g_sexp[t][0] = expf((float)(m0 * 10.0));
    g_sexp[t][1] = expf((float)(m1 * 10.0));
    g_sexp[t][2] = expf((float)(m2 * 10.0));
    g_cnt[t] = ex ? (float)cnt : 0.f;

    atomicAdd(&sobj[b], ex ? 1.f : 0.f);
    atomicAdd(&svar[b], (float)var);
    __syncthreads();
    if (t < BN) {
        g_denom[t]  = sobj[t] > 1.f ? sobj[t] : 1.f;
        g_varsum[t] = svar[t];
    }
}

// ---------------- pass 3: per-(b,id,slice) histograms + seed loss ----------------
// one packed u64 shared atomic per voxel-id: (count<<32) | (ti & 16383)
// ti = floor(t*16384), t = e*2048 in [0,4096)
#define K3_BODY(S, IV)                                                          \
    {                                                                           \
        float dx = S.x - c0, dy = S.y - c1, dz = S.z - c2;                      \
        float d2 = fmaf(dx*dx, e0, fmaf(dy*dy, e1, dz*dz*e2));                  \
        float dist = __expf(-d2);                                               \
        bool gt = (IV == id);                                                   \
        float t = gt ? (4096.f - 4096.f*dist) : (4096.f*dist);                  \
        unsigned ti = __float2uint_rz(t * 16384.f);                             \
        ti = ti > 67108863u ? 67108863u : ti;                                   \
        unsigned off = (ti >> 14) + (gt ? NB : 0);                              \
        atomicAdd(&sh[off], (1ULL << 32) | (unsigned long long)(ti & 16383u));  \
        if (gt) { float df = S.w - dist; sacc += df * df; }                     \
    }

__global__ void __launch_bounds__(512, 3) k3() {
    extern __shared__ unsigned long long sh[];     // 2*NB u64 = 64KB
    __shared__ float swr[16];

    int b = blockIdx.z, idm1 = blockIdx.x;
    int bi = b * NID + idm1;
    unsigned id = idm1 + 1;
    float G = g_cnt[bi];
    if (G == 0.f) return;

    float c0 = g_center[bi][0], c1 = g_center[bi][1], c2 = g_center[bi][2];
    float e0 = g_sexp[bi][0],   e1 = g_sexp[bi][1],   e2 = g_sexp[bi][2];

    int tid = threadIdx.x;
    for (int i = tid; i < 2*NB; i += 512) sh[i] = 0ULL;
    __syncthreads();

    const float4* __restrict__ se = g_se + (size_t)b * DHW;
    const unsigned char* __restrict__ idp = g_id8 + (size_t)b * DHW;
    float sacc = 0.f;
    int v0 = blockIdx.y * CH;
    int vend = v0 + CH; if (vend > DHW) vend = DHW;

    int v = v0 + tid;
    for (; v + 512 < vend; v += 1024) {
        float4 sA = se[v];        unsigned ivA = idp[v];
        float4 sB = se[v + 512];  unsigned ivB = idp[v + 512];
        K3_BODY(sA, ivA)
        K3_BODY(sB, ivB)
    }
    for (; v < vend; v += 512) {
        float4 sA = se[v]; unsigned ivA = idp[v];
        K3_BODY(sA, ivA)
    }

    // warp-reduce seed loss
    for (int o = 16; o; o >>= 1) sacc += __shfl_down_sync(0xffffffffu, sacc, o);
    if ((tid & 31) == 0) swr[tid >> 5] = sacc;
    __syncthreads();
    if (tid == 0) {
        double s = 0.0;
        for (int i = 0; i < 16; i++) s += (double)swr[i];
        atomicAdd(&g_seedl[b], s);
    }
    // dump partial histogram (plain stores, no atomics)
    unsigned long long* dst = g_part[bi][blockIdx.y];
    for (int i = tid; i < 2*NB; i += 512) dst[i] = sh[i];
}

// ---------------- pass 4: Lovasz via histogram scan ----------------
#define NT4 512
#define PER4 (NB / NT4)   // 8
__global__ void k4() {
    extern __shared__ float sf[];   // pc[NB], nc[NB], ps[NB], ns[NB] = 64KB
    float* pc = sf;
    float* nc = sf + NB;
    float* ps = sf + 2*NB;
    float* ns = sf + 3*NB;
    __shared__ float sp[NT4], sn[NT4];
    __shared__ double sctr[NT4];

    int bi = blockIdx.x, b = bi / NID;
    float G = g_cnt[bi];
    if (G == 0.f) return;
    int t = threadIdx.x;

    float tp = 0.f, tn = 0.f;
    #pragma unroll
    for (int i = 0; i < PER4; i++) {
        int k = t * PER4 + i;        // descending-order position
        int j = NB - 1 - k;          // bin index
        unsigned long long cp = 0, rp = 0, cn = 0, rn = 0;
        #pragma unroll
        for (int s = 0; s < SLICES; s++) {
            unsigned long long vp = g_part[bi][s][NB + j];
            unsigned long long vn = g_part[bi][s][j];
            cp += vp >> 32; rp += vp & 0xffffffffULL;
            cn += vn >> 32; rn += vn & 0xffffffffULL;
        }
        float fp = (float)cp, fn = (float)cn;
        pc[k] = fp; nc[k] = fn;
        ps[k] = (float)(((double)cp * (double)j + (double)rp * (1.0/16384.0)) * (1.0/2048.0));
        ns[k] = (float)(((double)cn * (double)j + (double)rn * (1.0/16384.0)) * (1.0/2048.0));
        tp += fp; tn += fn;
    }
    sp[t] = tp; sn[t] = tn;
    __syncthreads();
    for (int o = 1; o < NT4; o <<= 1) {
        float ap = (t >= o) ? sp[t - o] : 0.f;
        float an = (t >= o) ? sn[t - o] : 0.f;
        __syncthreads();
        sp[t] += ap; sn[t] += an;
        __syncthreads();
    }
    float P = sp[t] - tp;   // exclusive cumulative positives before this thread's bins
    float N = sn[t] - tn;

    double contrib = 0.0;
    #pragma unroll
    for (int i = 0; i < PER4; i++) {
        int k = t * PER4 + i;
        float p = pc[k], n = nc[k];
        double U0 = (double)G + (double)N;
        double U1 = U0 + (double)n;
        // average of pos-first and neg-first within-bin orderings:
        if (p > 0.f) contrib += (double)ps[k] * 0.5 * (1.0/U0 + 1.0/U1);
        if (n > 0.f) contrib += (double)ns[k] *
                                ((double)G - (double)P - 0.5*(double)p) / (U0 * U1);
        P += p; N += n;
    }
    sctr[t] = contrib;
    __syncthreads();
    for (int o = NT4/2; o > 0; o >>= 1) {
        if (t < o) sctr[t] += sctr[t + o];
        __syncthreads();
    }
    if (t == 0) atomicAdd(&g_instl[b], sctr[0]);
}

// ---------------- pass 5: final reduction ----------------
__global__ void k5(float* __restrict__ out) {
    double li = 0.0, lv = 0.0, ls = 0.0;
    for (int b = 0; b < BN; b++) {
        li += g_instl[b] / (double)g_denom[b];
        lv += (double)g_varsum[b] / (double)g_denom[b];
        ls += (g_seedl[b] + g_bg[b]) / (double)DHW;
    }
    li /= (double)BN;
    lv = lv * 10.0 / (double)BN;   // W_VAR = 10
    ls /= (double)BN;
    out[0] = (float)li;
    out[1] = (float)lv;
    out[2] = (float)ls;
    out[3] = (float)(li + lv + ls);
}

// ---------------- launch ----------------
extern "C" void kernel_launch(void* const* d_in, const int* in_sizes, int n_in,
                              void* d_out, int out_size) {
    const float* pred = (const float*)d_in[0];
    const int*   inst = (const int*)d_in[1];
    const int*   lab  = (const int*)d_in[2];
    // d_in[3] = center_images (unused by the loss)
    const float* xyzm = (const float*)d_in[4];

    cudaFuncSetAttribute(k3, cudaFuncAttributeMaxDynamicSharedMemorySize, 2*NB*8);
    cudaFuncSetAttribute(k4, cudaFuncAttributeMaxDynamicSharedMemorySize, 4*NB*4);

    kzero<<<1, 640>>>();
    k1<<<dim3(288, BN), 256>>>(pred, inst, lab, xyzm);
    k2<<<1, 64>>>();
    k3<<<dim3(NID, SLICES, BN), 512, 2*NB*8>>>();
    k4<<<NBI, NT4, 4*NB*4>>>();
    k5<<<1, 1>>>((float*)d_out);
}